// round 7
// baseline (speedup 1.0000x reference)
#include <cuda_runtime.h>
#include <math.h>

#define BATCH 2
#define C 64
#define H 80
#define W 80
#define HW 6400

// ---- scratch layout (floats) ----
#define OFF3 0
#define OFF5 345600            // 2*27*6400
#define OFF7 1305600           // + 2*75*6400
#define WT3  3187200           // + 2*147*6400
#define WT5  3224064           // + 9*4096
#define WT7  3326464           // + 25*4096
#define SCRATCH_TOTAL 3527168  // + 49*4096

__device__ float g_scratch[SCRATCH_TOTAL];

// ============================================================
// Merged transpose: w_dcn[oc][c][tap] -> wt[tap][c][oc], all 3 branches
// ============================================================
__global__ void transpose_all(const float* __restrict__ w3,
                              const float* __restrict__ w5,
                              const float* __restrict__ w7) {
    int i = blockIdx.x * 256 + threadIdx.x;
    if (i >= 83 * 4096) return;
    const float* src; int KK, base;
    if (i < 9 * 4096)       { src = w3; KK = 9;  base = WT3; }
    else if (i < 34 * 4096) { src = w5; KK = 25; base = WT5; i -= 9 * 4096; }
    else                    { src = w7; KK = 49; base = WT7; i -= 34 * 4096; }
    int tap = i >> 12;
    int r = i & 4095;
    int c = r >> 6;
    int oc = r & 63;
    g_scratch[base + i] = src[(oc * 64 + c) * KK + tap];
}

// ============================================================
// Conv body (templated on K). 16x16 px tile, 32 oc / block.
// Weight smem rows strided to 40 floats -> 2x LDS.128 broadcast per thread.
// x row segment register-hoisted across kx. (unchanged from R4 - measured good)
// ============================================================
#define CONV_SMEM_FLOATS 9864   // K=7: xp 4*22*23=2024 + ws 4*49*40=7840

template <int K>
__device__ __forceinline__ void conv_body(
    float* sm, const float* __restrict__ x,
    const float* __restrict__ w_off, const float* __restrict__ b_off,
    const float* __restrict__ w_msk, const float* __restrict__ b_msk,
    int offbase, int id, int nOCB)
{
    constexpr int KK  = K * K;
    constexpr int CH  = 3 * KK;
    constexpr int PAD = K / 2;
    constexpr int PH  = 16 + K - 1;
    constexpr int PWP = PH + 1;
    constexpr int CC  = 4;
    constexpr int XPN = CC * PH * PWP;

    float* xp = sm;            // [CC][PH][PWP]
    float* ws = sm + XPN;      // [CC][KK][40]

    const int tid = threadIdx.x;
    const int bxx = id % 5;
    const int byy = (id / 5) % 5;
    const int z   = id / 25;
    const int b   = z / nOCB;
    const int ocb = z % nOCB;
    const int ty  = byy * 16;
    const int tx  = bxx * 16;

    const int ocg  = tid >> 6;
    const int pixg = tid & 63;
    const int py   = pixg & 15;
    const int px4  = (pixg >> 4) * 4;

    float acc[8][4];
    #pragma unroll
    for (int j = 0; j < 8; j++)
        #pragma unroll
        for (int i = 0; i < 4; i++) acc[j][i] = 0.f;

    for (int c0 = 0; c0 < C; c0 += CC) {
        __syncthreads();
        for (int l = tid; l < CC * PH * PH; l += 256) {
            int cc = l / (PH * PH);
            int r  = l % (PH * PH);
            int ly = r / PH, lx = r % PH;
            int gy = ty - PAD + ly, gx = tx - PAD + lx;
            float v = 0.f;
            if (gy >= 0 && gy < H && gx >= 0 && gx < W)
                v = x[((b * C + c0 + cc) * H + gy) * W + gx];
            xp[(cc * PH + ly) * PWP + lx] = v;
        }
        for (int l = tid; l < 32 * CC * KK; l += 256) {
            int ocl = l / (CC * KK);
            int r   = l % (CC * KK);
            int cc  = r / KK, tap = r % KK;
            int oc  = ocb * 32 + ocl;
            float v = 0.f;
            if (oc < 2 * KK)  v = w_off[(oc * C + c0 + cc) * KK + tap];
            else if (oc < CH) v = w_msk[((oc - 2 * KK) * C + c0 + cc) * KK + tap];
            ws[(cc * KK + tap) * 40 + ocl] = v;
        }
        __syncthreads();

        #pragma unroll 1
        for (int cc = 0; cc < CC; cc++) {
            #pragma unroll 1
            for (int ky = 0; ky < K; ky++) {
                float xr[K + 3];
                const float* xrow = &xp[(cc * PH + py + ky) * PWP + px4];
                #pragma unroll
                for (int i = 0; i < K + 3; i++) xr[i] = xrow[i];
                #pragma unroll
                for (int kx = 0; kx < K; kx++) {
                    const float4* wv =
                        (const float4*)&ws[(cc * KK + ky * K + kx) * 40 + ocg * 8];
                    float4 wa = wv[0];
                    float4 wb = wv[1];
                    float ww[8];
                    ww[0] = wa.x; ww[1] = wa.y; ww[2] = wa.z; ww[3] = wa.w;
                    ww[4] = wb.x; ww[5] = wb.y; ww[6] = wb.z; ww[7] = wb.w;
                    #pragma unroll
                    for (int j = 0; j < 8; j++) {
                        acc[j][0] += ww[j] * xr[kx + 0];
                        acc[j][1] += ww[j] * xr[kx + 1];
                        acc[j][2] += ww[j] * xr[kx + 2];
                        acc[j][3] += ww[j] * xr[kx + 3];
                    }
                }
            }
        }
    }

    #pragma unroll 1
    for (int j = 0; j < 8; j++) {
        int oc = ocb * 32 + ocg * 8 + j;
        if (oc >= CH) break;
        bool ismask = (oc >= 2 * KK);
        float bias = ismask ? b_msk[oc - 2 * KK] : b_off[oc];
        float* dst = &g_scratch[offbase + (b * CH + oc) * HW + (ty + py) * W + tx + px4];
        #pragma unroll
        for (int i = 0; i < 4; i++) {
            float v = acc[j][i] + bias;
            if (ismask) v = 1.f / (1.f + __expf(-v));
            dst[i] = v;
        }
    }
}

__global__ __launch_bounds__(256) void conv_all(
    const float* __restrict__ x,
    const float* __restrict__ wo3, const float* __restrict__ bo3,
    const float* __restrict__ wm3, const float* __restrict__ bm3,
    const float* __restrict__ wo5, const float* __restrict__ bo5,
    const float* __restrict__ wm5, const float* __restrict__ bm5,
    const float* __restrict__ wo7, const float* __restrict__ bo7,
    const float* __restrict__ wm7, const float* __restrict__ bm7)
{
    __shared__ float sm[CONV_SMEM_FLOATS];
    int bx = blockIdx.x;
    if (bx < 250)      conv_body<7>(sm, x, wo7, bo7, wm7, bm7, OFF7, bx, 5);
    else if (bx < 400) conv_body<5>(sm, x, wo5, bo5, wm5, bm5, OFF5, bx - 250, 3);
    else               conv_body<3>(sm, x, wo3, bo3, wm3, bm3, OFF3, bx - 400, 1);
}

// ============================================================
// Deform: 128 px, 64 oc per block, 256 threads, dynamic smem (52KB).
// Per tap: [load wtile + corner precompute] -> gather -> GEMM.
// Each warp owns one 8-oc group (weight LDS are warp-uniform broadcast).
// ============================================================
#define DEF_SMEM_BYTES ((8192 + 4096 + 512 + 512) * 4)   // 53248

template <int K>
__device__ __forceinline__ void deform_body(
    float* samp,            // [64][128]
    float* wtile,           // [64][64]
    float (*cw)[4],         // [128][4]
    int (*cidx)[4],         // [128][4]
    const float* __restrict__ x, int offbase, int wtbase,
    float* __restrict__ out, int obase, int b, int p0)
{
    constexpr int KK  = K * K;
    constexpr int CH  = 3 * KK;
    constexpr int PAD = K / 2;

    const int tid = threadIdx.x;
    const int pixg = tid & 31;   // float4 column 0..31 (4 px each)
    const int ocg  = tid >> 5;   // warp id = oc group (8 oc each)

    float4 acc[8];
    #pragma unroll
    for (int j = 0; j < 8; j++) acc[j] = make_float4(0.f, 0.f, 0.f, 0.f);

    const float* xb = x + b * C * HW;
    const float4* wtg = (const float4*)(g_scratch + wtbase);
    const float* ob = g_scratch + offbase + b * CH * HW;

    #pragma unroll 1
    for (int tap = 0; tap < KK; tap++) {
        __syncthreads();   // previous GEMM done reading samp/wtile

        // weight slice [c][oc] for this tap (16KB) : 4 float4 per thread
        {
            float4* w4 = (float4*)wtile;
            const float4* src = wtg + tap * 1024;
            #pragma unroll
            for (int l = 0; l < 4; l++) w4[tid + l * 256] = src[tid + l * 256];
        }
        // per-pixel corner data (128 pixels)
        if (tid < 128) {
            int p = p0 + tid;
            int h = p / W, w = p % W;
            float oy = ob[(2 * tap) * HW + p];
            float ox = ob[(2 * tap + 1) * HW + p];
            float m  = ob[(2 * KK + tap) * HW + p];
            float py = (float)(h - PAD + tap / K) + oy;
            float px = (float)(w - PAD + tap % K) + ox;
            float y0f = floorf(py), x0f = floorf(px);
            float fy = py - y0f, fx = px - x0f;
            int y0 = (int)y0f, x0 = (int)x0f;
            int y1 = y0 + 1, x1 = x0 + 1;
            bool vy0 = (y0 >= 0) && (y0 < H);
            bool vy1 = (y1 >= 0) && (y1 < H);
            bool vx0 = (x0 >= 0) && (x0 < W);
            bool vx1 = (x1 >= 0) && (x1 < W);
            int y0c = min(max(y0, 0), H - 1), y1c = min(max(y1, 0), H - 1);
            int x0c = min(max(x0, 0), W - 1), x1c = min(max(x1, 0), W - 1);
            cw[tid][0] = (vy0 && vx0) ? (1.f - fy) * (1.f - fx) * m : 0.f;
            cw[tid][1] = (vy0 && vx1) ? (1.f - fy) * fx * m : 0.f;
            cw[tid][2] = (vy1 && vx0) ? fy * (1.f - fx) * m : 0.f;
            cw[tid][3] = (vy1 && vx1) ? fy * fx * m : 0.f;
            cidx[tid][0] = y0c * W + x0c;
            cidx[tid][1] = y0c * W + x1c;
            cidx[tid][2] = y1c * W + x0c;
            cidx[tid][3] = y1c * W + x1c;
        }
        __syncthreads();

        // bilinear gather: 1 pixel per thread, 32 channels each
        {
            int pix = tid & 127;
            int ch0 = (tid >> 7) * 32;
            float w0 = cw[pix][0], w1 = cw[pix][1];
            float w2 = cw[pix][2], w3 = cw[pix][3];
            int i0 = cidx[pix][0], i1 = cidx[pix][1];
            int i2 = cidx[pix][2], i3 = cidx[pix][3];
            #pragma unroll 4
            for (int cc = 0; cc < 32; cc++) {
                const float* xc = xb + (ch0 + cc) * HW;
                samp[(ch0 + cc) * 128 + pix] =
                    w0 * xc[i0] + w1 * xc[i1] + w2 * xc[i2] + w3 * xc[i3];
            }
        }
        __syncthreads();

        // GEMM accumulate: out[oc][pix] += wtile[c][oc] * samp[c][pix]
        {
            const float4* s4 = (const float4*)samp;
            const float4* w4 = (const float4*)wtile;
            #pragma unroll 4
            for (int c = 0; c < 64; c++) {
                float4 s  = s4[c * 32 + pixg];
                float4 wa = w4[c * 16 + ocg * 2];
                float4 wb = w4[c * 16 + ocg * 2 + 1];
                float ww[8];
                ww[0] = wa.x; ww[1] = wa.y; ww[2] = wa.z; ww[3] = wa.w;
                ww[4] = wb.x; ww[5] = wb.y; ww[6] = wb.z; ww[7] = wb.w;
                #pragma unroll
                for (int j = 0; j < 8; j++) {
                    acc[j].x += ww[j] * s.x;
                    acc[j].y += ww[j] * s.y;
                    acc[j].z += ww[j] * s.z;
                    acc[j].w += ww[j] * s.w;
                }
            }
        }
    }

    float4* o4 = (float4*)out;
    #pragma unroll
    for (int j = 0; j < 8; j++) {
        int oc = ocg * 8 + j;
        o4[((b * 192 + obase + oc) * HW + p0) / 4 + pixg] = acc[j];
    }
}

// Merged deform kernel: K=7 blocks first. 50 tiles of 128 px per branch.
__global__ __launch_bounds__(256) void deform_all(
    const float* __restrict__ x, float* __restrict__ out)
{
    extern __shared__ float dyn[];
    float* samp  = dyn;                      // 8192
    float* wtile = dyn + 8192;               // 4096
    float (*cw)[4]  = (float(*)[4])(dyn + 8192 + 4096);        // 512
    int   (*cidx)[4] = (int(*)[4])(dyn + 8192 + 4096 + 512);   // 512

    int bx = blockIdx.x;
    int b  = blockIdx.y;
    if (bx < 50)
        deform_body<7>(samp, wtile, cw, cidx, x, OFF7, WT7, out, 128, b, bx * 128);
    else if (bx < 100)
        deform_body<5>(samp, wtile, cw, cidx, x, OFF5, WT5, out, 64, b, (bx - 50) * 128);
    else
        deform_body<3>(samp, wtile, cw, cidx, x, OFF3, WT3, out, 0, b, (bx - 100) * 128);
}

// ============================================================
extern "C" void kernel_launch(void* const* d_in, const int* in_sizes, int n_in,
                              void* d_out, int out_size) {
    (void)in_sizes; (void)n_in; (void)out_size;
    const float* x       = (const float*)d_in[0];
    const float* w_off3  = (const float*)d_in[1];
    const float* b_off3  = (const float*)d_in[2];
    const float* w_msk3  = (const float*)d_in[3];
    const float* b_msk3  = (const float*)d_in[4];
    const float* w_dcn3  = (const float*)d_in[5];
    const float* w_off5  = (const float*)d_in[6];
    const float* b_off5  = (const float*)d_in[7];
    const float* w_msk5  = (const float*)d_in[8];
    const float* b_msk5  = (const float*)d_in[9];
    const float* w_dcn5  = (const float*)d_in[10];
    const float* w_off7  = (const float*)d_in[11];
    const float* b_off7  = (const float*)d_in[12];
    const float* w_msk7  = (const float*)d_in[13];
    const float* b_msk7  = (const float*)d_in[14];
    const float* w_dcn7  = (const float*)d_in[15];
    float* out = (float*)d_out;

    static bool attr_set = false;
    if (!attr_set) {
        cudaFuncSetAttribute(deform_all,
                             cudaFuncAttributeMaxDynamicSharedMemorySize,
                             DEF_SMEM_BYTES);
        attr_set = true;
    }

    // conv first (independent of transpose) so ncu's skip-5 capture lands on
    // deform_all instead of transpose_all.
    conv_all<<<450, 256>>>(x,
        w_off3, b_off3, w_msk3, b_msk3,
        w_off5, b_off5, w_msk5, b_msk5,
        w_off7, b_off7, w_msk7, b_msk7);

    transpose_all<<<(83 * 4096 + 255) / 256, 256>>>(w_dcn3, w_dcn5, w_dcn7);

    deform_all<<<dim3(150, BATCH), 256, DEF_SMEM_BYTES>>>(x, out);
}

// round 9
// speedup vs baseline: 1.0936x; 1.0936x over previous
#include <cuda_runtime.h>
#include <math.h>

#define BATCH 2
#define C 64
#define H 80
#define W 80
#define HW 6400

// ---- scratch layout (floats) ----
#define OFF3 0
#define OFF5 345600            // 2*27*6400
#define OFF7 1305600           // + 2*75*6400
#define WT3  3187200           // + 2*147*6400
#define WT5  3224064           // + 9*4096
#define WT7  3326464           // + 25*4096
#define SCRATCH_TOTAL 3527168  // + 49*4096

__device__ float g_scratch[SCRATCH_TOTAL];

// ============================================================
// Transpose split in two so the capture index (4th launch) hits deform_all.
// w_dcn[oc][c][tap] -> wt[tap][c][oc]
// ============================================================
__global__ void transpose_a(const float* __restrict__ w3,
                            const float* __restrict__ w5) {
    int i = blockIdx.x * 256 + threadIdx.x;
    if (i >= 34 * 4096) return;
    const float* src; int KK, base;
    if (i < 9 * 4096) { src = w3; KK = 9;  base = WT3; }
    else              { src = w5; KK = 25; base = WT5; i -= 9 * 4096; }
    int tap = i >> 12;
    int r = i & 4095;
    int c = r >> 6;
    int oc = r & 63;
    g_scratch[base + i] = src[(oc * 64 + c) * KK + tap];
}

__global__ void transpose_b(const float* __restrict__ w7) {
    int i = blockIdx.x * 256 + threadIdx.x;
    if (i >= 49 * 4096) return;
    int tap = i >> 12;
    int r = i & 4095;
    int c = r >> 6;
    int oc = r & 63;
    g_scratch[WT7 + i] = w7[(oc * 64 + c) * 49 + tap];
}

// ============================================================
// Conv body (templated on K). 16x16 px tile, 32 oc / block.
// Weight smem rows strided to 40 floats -> 2x LDS.128 broadcast per thread.
// x row segment register-hoisted across kx.
// ============================================================
#define CONV_SMEM_FLOATS 9864   // K=7: xp 4*22*23=2024 + ws 4*49*40=7840

template <int K>
__device__ __forceinline__ void conv_body(
    float* sm, const float* __restrict__ x,
    const float* __restrict__ w_off, const float* __restrict__ b_off,
    const float* __restrict__ w_msk, const float* __restrict__ b_msk,
    int offbase, int id, int nOCB)
{
    constexpr int KK  = K * K;
    constexpr int CH  = 3 * KK;
    constexpr int PAD = K / 2;
    constexpr int PH  = 16 + K - 1;
    constexpr int PWP = PH + 1;
    constexpr int CC  = 4;
    constexpr int XPN = CC * PH * PWP;

    float* xp = sm;            // [CC][PH][PWP]
    float* ws = sm + XPN;      // [CC][KK][40]

    const int tid = threadIdx.x;
    const int bxx = id % 5;
    const int byy = (id / 5) % 5;
    const int z   = id / 25;
    const int b   = z / nOCB;
    const int ocb = z % nOCB;
    const int ty  = byy * 16;
    const int tx  = bxx * 16;

    const int ocg  = tid >> 6;
    const int pixg = tid & 63;
    const int py   = pixg & 15;
    const int px4  = (pixg >> 4) * 4;

    float acc[8][4];
    #pragma unroll
    for (int j = 0; j < 8; j++)
        #pragma unroll
        for (int i = 0; i < 4; i++) acc[j][i] = 0.f;

    for (int c0 = 0; c0 < C; c0 += CC) {
        __syncthreads();
        for (int l = tid; l < CC * PH * PH; l += 256) {
            int cc = l / (PH * PH);
            int r  = l % (PH * PH);
            int ly = r / PH, lx = r % PH;
            int gy = ty - PAD + ly, gx = tx - PAD + lx;
            float v = 0.f;
            if (gy >= 0 && gy < H && gx >= 0 && gx < W)
                v = x[((b * C + c0 + cc) * H + gy) * W + gx];
            xp[(cc * PH + ly) * PWP + lx] = v;
        }
        for (int l = tid; l < 32 * CC * KK; l += 256) {
            int ocl = l / (CC * KK);
            int r   = l % (CC * KK);
            int cc  = r / KK, tap = r % KK;
            int oc  = ocb * 32 + ocl;
            float v = 0.f;
            if (oc < 2 * KK)  v = w_off[(oc * C + c0 + cc) * KK + tap];
            else if (oc < CH) v = w_msk[((oc - 2 * KK) * C + c0 + cc) * KK + tap];
            ws[(cc * KK + tap) * 40 + ocl] = v;
        }
        __syncthreads();

        #pragma unroll 1
        for (int cc = 0; cc < CC; cc++) {
            #pragma unroll 1
            for (int ky = 0; ky < K; ky++) {
                float xr[K + 3];
                const float* xrow = &xp[(cc * PH + py + ky) * PWP + px4];
                #pragma unroll
                for (int i = 0; i < K + 3; i++) xr[i] = xrow[i];
                #pragma unroll
                for (int kx = 0; kx < K; kx++) {
                    const float4* wv =
                        (const float4*)&ws[(cc * KK + ky * K + kx) * 40 + ocg * 8];
                    float4 wa = wv[0];
                    float4 wb = wv[1];
                    float ww[8];
                    ww[0] = wa.x; ww[1] = wa.y; ww[2] = wa.z; ww[3] = wa.w;
                    ww[4] = wb.x; ww[5] = wb.y; ww[6] = wb.z; ww[7] = wb.w;
                    #pragma unroll
                    for (int j = 0; j < 8; j++) {
                        acc[j][0] += ww[j] * xr[kx + 0];
                        acc[j][1] += ww[j] * xr[kx + 1];
                        acc[j][2] += ww[j] * xr[kx + 2];
                        acc[j][3] += ww[j] * xr[kx + 3];
                    }
                }
            }
        }
    }

    #pragma unroll 1
    for (int j = 0; j < 8; j++) {
        int oc = ocb * 32 + ocg * 8 + j;
        if (oc >= CH) break;
        bool ismask = (oc >= 2 * KK);
        float bias = ismask ? b_msk[oc - 2 * KK] : b_off[oc];
        float* dst = &g_scratch[offbase + (b * CH + oc) * HW + (ty + py) * W + tx + px4];
        #pragma unroll
        for (int i = 0; i < 4; i++) {
            float v = acc[j][i] + bias;
            if (ismask) v = 1.f / (1.f + __expf(-v));
            dst[i] = v;
        }
    }
}

// minBlocksPerMultiprocessor=4 -> ptxas targets <=64 regs -> 32 warps/SM
__global__ __launch_bounds__(256, 4) void conv_all(
    const float* __restrict__ x,
    const float* __restrict__ wo3, const float* __restrict__ bo3,
    const float* __restrict__ wm3, const float* __restrict__ bm3,
    const float* __restrict__ wo5, const float* __restrict__ bo5,
    const float* __restrict__ wm5, const float* __restrict__ bm5,
    const float* __restrict__ wo7, const float* __restrict__ bo7,
    const float* __restrict__ wm7, const float* __restrict__ bm7)
{
    __shared__ float sm[CONV_SMEM_FLOATS];
    int bx = blockIdx.x;
    if (bx < 250)      conv_body<7>(sm, x, wo7, bo7, wm7, bm7, OFF7, bx, 5);
    else if (bx < 400) conv_body<5>(sm, x, wo5, bo5, wm5, bm5, OFF5, bx - 250, 3);
    else               conv_body<3>(sm, x, wo3, bo3, wm3, bm3, OFF3, bx - 400, 1);
}

// ============================================================
// Deform (R6 measured-good version): 64 px, 64 oc per block, 128 threads.
// ============================================================
template <int K>
__device__ __forceinline__ void deform_body(
    float* samp, float* wtile, float (*cw)[4], int (*cidx)[4],
    const float* __restrict__ x, int offbase, int wtbase,
    float* __restrict__ out, int obase, int b, int p0)
{
    constexpr int KK  = K * K;
    constexpr int CH  = 3 * KK;
    constexpr int PAD = K / 2;

    const int tid = threadIdx.x;
    const int pixg = tid & 15;   // 4 px each
    const int ocg  = tid >> 4;   // 8 oc each

    float4 acc[8];
    #pragma unroll
    for (int j = 0; j < 8; j++) acc[j] = make_float4(0.f, 0.f, 0.f, 0.f);

    const float* xb = x + b * C * HW;
    const float4* wtg = (const float4*)(g_scratch + wtbase);
    const float* ob = g_scratch + offbase + b * CH * HW;

    #pragma unroll 1
    for (int tap = 0; tap < KK; tap++) {
        __syncthreads();

        {
            float4* w4 = (float4*)wtile;
            const float4* src = wtg + tap * 1024;
            for (int l = tid; l < 1024; l += 128) w4[l] = src[l];
        }
        if (tid < 64) {
            int p = p0 + tid;
            int h = p / W, w = p % W;
            float oy = ob[(2 * tap) * HW + p];
            float ox = ob[(2 * tap + 1) * HW + p];
            float m  = ob[(2 * KK + tap) * HW + p];
            float py = (float)(h - PAD + tap / K) + oy;
            float px = (float)(w - PAD + tap % K) + ox;
            float y0f = floorf(py), x0f = floorf(px);
            float fy = py - y0f, fx = px - x0f;
            int y0 = (int)y0f, x0 = (int)x0f;
            int y1 = y0 + 1, x1 = x0 + 1;
            bool vy0 = (y0 >= 0) && (y0 < H);
            bool vy1 = (y1 >= 0) && (y1 < H);
            bool vx0 = (x0 >= 0) && (x0 < W);
            bool vx1 = (x1 >= 0) && (x1 < W);
            int y0c = min(max(y0, 0), H - 1), y1c = min(max(y1, 0), H - 1);
            int x0c = min(max(x0, 0), W - 1), x1c = min(max(x1, 0), W - 1);
            cw[tid][0] = (vy0 && vx0) ? (1.f - fy) * (1.f - fx) * m : 0.f;
            cw[tid][1] = (vy0 && vx1) ? (1.f - fy) * fx * m : 0.f;
            cw[tid][2] = (vy1 && vx0) ? fy * (1.f - fx) * m : 0.f;
            cw[tid][3] = (vy1 && vx1) ? fy * fx * m : 0.f;
            cidx[tid][0] = y0c * W + x0c;
            cidx[tid][1] = y0c * W + x1c;
            cidx[tid][2] = y1c * W + x0c;
            cidx[tid][3] = y1c * W + x1c;
        }
        __syncthreads();

        {
            int pix = tid & 63;
            int ch0 = (tid >> 6) * 32;
            float w0 = cw[pix][0], w1 = cw[pix][1];
            float w2 = cw[pix][2], w3 = cw[pix][3];
            int i0 = cidx[pix][0], i1 = cidx[pix][1];
            int i2 = cidx[pix][2], i3 = cidx[pix][3];
            #pragma unroll 4
            for (int cc = 0; cc < 32; cc++) {
                const float* xc = xb + (ch0 + cc) * HW;
                samp[(ch0 + cc) * 64 + pix] =
                    w0 * xc[i0] + w1 * xc[i1] + w2 * xc[i2] + w3 * xc[i3];
            }
        }
        __syncthreads();

        {
            const float4* s4 = (const float4*)samp;
            const float4* w4 = (const float4*)wtile;
            #pragma unroll 4
            for (int c = 0; c < 64; c++) {
                float4 s  = s4[c * 16 + pixg];
                float4 wa = w4[c * 16 + ocg * 2];
                float4 wb = w4[c * 16 + ocg * 2 + 1];
                float ww[8];
                ww[0] = wa.x; ww[1] = wa.y; ww[2] = wa.z; ww[3] = wa.w;
                ww[4] = wb.x; ww[5] = wb.y; ww[6] = wb.z; ww[7] = wb.w;
                #pragma unroll
                for (int j = 0; j < 8; j++) {
                    acc[j].x += ww[j] * s.x;
                    acc[j].y += ww[j] * s.y;
                    acc[j].z += ww[j] * s.z;
                    acc[j].w += ww[j] * s.w;
                }
            }
        }
    }

    float4* o4 = (float4*)out;
    #pragma unroll
    for (int j = 0; j < 8; j++) {
        int oc = ocg * 8 + j;
        o4[((b * 192 + obase + oc) * HW + p0) / 4 + pixg] = acc[j];
    }
}

__global__ __launch_bounds__(128) void deform_all(
    const float* __restrict__ x, float* __restrict__ out)
{
    __shared__ float samp[64 * 64];
    __shared__ float wtile[64 * 64];
    __shared__ float cw[64][4];
    __shared__ int   cidx[64][4];

    int bx = blockIdx.x;
    int b  = blockIdx.y;
    if (bx < 100)
        deform_body<7>(samp, wtile, cw, cidx, x, OFF7, WT7, out, 128, b, bx * 64);
    else if (bx < 200)
        deform_body<5>(samp, wtile, cw, cidx, x, OFF5, WT5, out, 64, b, (bx - 100) * 64);
    else
        deform_body<3>(samp, wtile, cw, cidx, x, OFF3, WT3, out, 0, b, (bx - 200) * 64);
}

// ============================================================
extern "C" void kernel_launch(void* const* d_in, const int* in_sizes, int n_in,
                              void* d_out, int out_size) {
    (void)in_sizes; (void)n_in; (void)out_size;
    const float* x       = (const float*)d_in[0];
    const float* w_off3  = (const float*)d_in[1];
    const float* b_off3  = (const float*)d_in[2];
    const float* w_msk3  = (const float*)d_in[3];
    const float* b_msk3  = (const float*)d_in[4];
    const float* w_dcn3  = (const float*)d_in[5];
    const float* w_off5  = (const float*)d_in[6];
    const float* b_off5  = (const float*)d_in[7];
    const float* w_msk5  = (const float*)d_in[8];
    const float* b_msk5  = (const float*)d_in[9];
    const float* w_dcn5  = (const float*)d_in[10];
    const float* w_off7  = (const float*)d_in[11];
    const float* b_off7  = (const float*)d_in[12];
    const float* w_msk7  = (const float*)d_in[13];
    const float* b_msk7  = (const float*)d_in[14];
    const float* w_dcn7  = (const float*)d_in[15];
    float* out = (float*)d_out;

    // 4 launches; captured profile index (4th launch) = deform_all.
    transpose_a<<<(34 * 4096 + 255) / 256, 256>>>(w_dcn3, w_dcn5);
    transpose_b<<<(49 * 4096 + 255) / 256, 256>>>(w_dcn7);

    conv_all<<<450, 256>>>(x,
        w_off3, b_off3, w_msk3, b_msk3,
        w_off5, b_off5, w_msk5, b_msk5,
        w_off7, b_off7, w_msk7, b_msk7);

    deform_all<<<dim3(300, BATCH), 128>>>(x, out);
}

// round 12
// speedup vs baseline: 1.1074x; 1.0126x over previous
#include <cuda_runtime.h>
#include <math.h>

#define BATCH 2
#define C 64
#define H 80
#define W 80
#define HW 6400

// ---- scratch layout (floats) ----
#define OFF3 0
#define OFF5 345600            // 2*27*6400
#define OFF7 1305600           // + 2*75*6400
#define WT3  3187200           // + 2*147*6400
#define WT5  3224064           // + 9*4096
#define WT7  3326464           // + 25*4096
#define CW3  3527168           // + 49*4096   conv weights [ocb][c][tap][40]
#define CW5  3550208           // + 1*64*9*40
#define CW7  3742208           // + 3*64*25*40
#define SCRATCH_TOTAL 4369408  // + 5*64*49*40

__device__ __align__(16) float g_scratch[SCRATCH_TOTAL];

// ============================================================
// conv weight prep: w_off/w_msk -> [ocb][c][tap][40] (smem-ready, zero-padded)
// ============================================================
__global__ void conv_prep(const float* __restrict__ wo3, const float* __restrict__ wm3,
                          const float* __restrict__ wo5, const float* __restrict__ wm5,
                          const float* __restrict__ wo7, const float* __restrict__ wm7) {
    int i = blockIdx.x * 256 + threadIdx.x;
    const float *wo, *wm; int KK, base;
    if (i < 23040)       { wo = wo3; wm = wm3; KK = 9;  base = CW3; }
    else if (i < 215040) { wo = wo5; wm = wm5; KK = 25; base = CW5; i -= 23040; }
    else if (i < 842240) { wo = wo7; wm = wm7; KK = 49; base = CW7; i -= 215040; }
    else return;
    int ocl = i % 40;
    int t   = i / 40;
    int tap = t % KK;
    int t2  = t / KK;
    int c   = t2 & 63;
    int ocb = t2 >> 6;
    int oc  = ocb * 32 + ocl;
    float v = 0.f;
    if (ocl < 32) {
        if (oc < 2 * KK)      v = wo[(oc * 64 + c) * KK + tap];
        else if (oc < 3 * KK) v = wm[((oc - 2 * KK) * 64 + c) * KK + tap];
    }
    g_scratch[base + i] = v;
}

// ============================================================
// Transposes for dcn weights: w_dcn[oc][c][tap] -> wt[tap][c][oc]
// ============================================================
__global__ void transpose_a(const float* __restrict__ w3,
                            const float* __restrict__ w5) {
    int i = blockIdx.x * 256 + threadIdx.x;
    if (i >= 34 * 4096) return;
    const float* src; int KK, base;
    if (i < 9 * 4096) { src = w3; KK = 9;  base = WT3; }
    else              { src = w5; KK = 25; base = WT5; i -= 9 * 4096; }
    int tap = i >> 12;
    int r = i & 4095;
    int c = r >> 6;
    int oc = r & 63;
    g_scratch[base + i] = src[(oc * 64 + c) * KK + tap];
}

__global__ void transpose_b(const float* __restrict__ w7) {
    int i = blockIdx.x * 256 + threadIdx.x;
    if (i >= 49 * 4096) return;
    int tap = i >> 12;
    int r = i & 4095;
    int c = r >> 6;
    int oc = r & 63;
    g_scratch[WT7 + i] = w7[(oc * 64 + c) * 49 + tap];
}

// ============================================================
// Conv body. 16x16 px tile, 32 oc / block. Weights arrive pre-transposed in
// g_scratch; per-chunk load is a contiguous float4 memcpy (coalesced, no math).
// ============================================================
#define CONV_SMEM_FLOATS 9864   // K=7: xp 4*22*23=2024 + ws 4*49*40=7840

template <int K>
__device__ __forceinline__ void conv_body(
    float* sm, const float* __restrict__ x,
    int cwbase, const float* __restrict__ b_off, const float* __restrict__ b_msk,
    int offbase, int id, int nOCB)
{
    constexpr int KK  = K * K;
    constexpr int CH  = 3 * KK;
    constexpr int PAD = K / 2;
    constexpr int PH  = 16 + K - 1;
    constexpr int PWP = PH + 1;
    constexpr int CC  = 4;
    constexpr int XPN = CC * PH * PWP;

    float* xp = sm;            // [CC][PH][PWP]
    float* ws = sm + XPN;      // [CC][KK][40]

    const int tid = threadIdx.x;
    const int bxx = id % 5;
    const int byy = (id / 5) % 5;
    const int z   = id / 25;
    const int b   = z / nOCB;
    const int ocb = z % nOCB;
    const int ty  = byy * 16;
    const int tx  = bxx * 16;

    const int ocg  = tid >> 6;
    const int pixg = tid & 63;
    const int py   = pixg & 15;
    const int px4  = (pixg >> 4) * 4;

    float acc[8][4];
    #pragma unroll
    for (int j = 0; j < 8; j++)
        #pragma unroll
        for (int i = 0; i < 4; i++) acc[j][i] = 0.f;

    for (int c0 = 0; c0 < C; c0 += CC) {
        __syncthreads();
        // x patch (zero-padded)
        for (int l = tid; l < CC * PH * PH; l += 256) {
            int cc = l / (PH * PH);
            int r  = l % (PH * PH);
            int ly = r / PH, lx = r % PH;
            int gy = ty - PAD + ly, gx = tx - PAD + lx;
            float v = 0.f;
            if (gy >= 0 && gy < H && gx >= 0 && gx < W)
                v = x[((b * C + c0 + cc) * H + gy) * W + gx];
            xp[(cc * PH + ly) * PWP + lx] = v;
        }
        // weights: contiguous float4 copy of this chunk's pre-transposed slice
        {
            constexpr int N4 = CC * KK * 10;   // (CC*KK*40)/4
            const float4* wsrc =
                (const float4*)&g_scratch[cwbase + ((ocb * 64 + c0) * KK) * 40];
            float4* wd = (float4*)ws;
            for (int l = tid; l < N4; l += 256) wd[l] = wsrc[l];
        }
        __syncthreads();

        #pragma unroll 1
        for (int cc = 0; cc < CC; cc++) {
            #pragma unroll 1
            for (int ky = 0; ky < K; ky++) {
                float xr[K + 3];
                const float* xrow = &xp[(cc * PH + py + ky) * PWP + px4];
                #pragma unroll
                for (int i = 0; i < K + 3; i++) xr[i] = xrow[i];
                #pragma unroll
                for (int kx = 0; kx < K; kx++) {
                    const float4* wv =
                        (const float4*)&ws[(cc * KK + ky * K + kx) * 40 + ocg * 8];
                    float4 wa = wv[0];
                    float4 wb = wv[1];
                    float ww[8];
                    ww[0] = wa.x; ww[1] = wa.y; ww[2] = wa.z; ww[3] = wa.w;
                    ww[4] = wb.x; ww[5] = wb.y; ww[6] = wb.z; ww[7] = wb.w;
                    #pragma unroll
                    for (int j = 0; j < 8; j++) {
                        acc[j][0] += ww[j] * xr[kx + 0];
                        acc[j][1] += ww[j] * xr[kx + 1];
                        acc[j][2] += ww[j] * xr[kx + 2];
                        acc[j][3] += ww[j] * xr[kx + 3];
                    }
                }
            }
        }
    }

    #pragma unroll 1
    for (int j = 0; j < 8; j++) {
        int oc = ocb * 32 + ocg * 8 + j;
        if (oc >= CH) break;
        bool ismask = (oc >= 2 * KK);
        float bias = ismask ? b_msk[oc - 2 * KK] : b_off[oc];
        float* dst = &g_scratch[offbase + (b * CH + oc) * HW + (ty + py) * W + tx + px4];
        #pragma unroll
        for (int i = 0; i < 4; i++) {
            float v = acc[j][i] + bias;
            if (ismask) v = 1.f / (1.f + __expf(-v));
            dst[i] = v;
        }
    }
}

// minBlocksPerMultiprocessor=4 -> ptxas targets <=64 regs -> 32 warps/SM
__global__ __launch_bounds__(256, 4) void conv_all(
    const float* __restrict__ x,
    const float* __restrict__ bo3, const float* __restrict__ bm3,
    const float* __restrict__ bo5, const float* __restrict__ bm5,
    const float* __restrict__ bo7, const float* __restrict__ bm7)
{
    __shared__ float sm[CONV_SMEM_FLOATS];
    int bx = blockIdx.x;
    if (bx < 250)      conv_body<7>(sm, x, CW7, bo7, bm7, OFF7, bx, 5);
    else if (bx < 400) conv_body<5>(sm, x, CW5, bo5, bm5, OFF5, bx - 250, 3);
    else               conv_body<3>(sm, x, CW3, bo3, bm3, OFF3, bx - 400, 1);
}

// ============================================================
// Deform (measured-good version): 64 px, 64 oc per block, 128 threads.
// ============================================================
template <int K>
__device__ __forceinline__ void deform_body(
    float* samp, float* wtile, float (*cw)[4], int (*cidx)[4],
    const float* __restrict__ x, int offbase, int wtbase,
    float* __restrict__ out, int obase, int b, int p0)
{
    constexpr int KK  = K * K;
    constexpr int CH  = 3 * KK;
    constexpr int PAD = K / 2;

    const int tid = threadIdx.x;
    const int pixg = tid & 15;   // 4 px each
    const int ocg  = tid >> 4;   // 8 oc each

    float4 acc[8];
    #pragma unroll
    for (int j = 0; j < 8; j++) acc[j] = make_float4(0.f, 0.f, 0.f, 0.f);

    const float* xb = x + b * C * HW;
    const float4* wtg = (const float4*)(g_scratch + wtbase);
    const float* ob = g_scratch + offbase + b * CH * HW;

    #pragma unroll 1
    for (int tap = 0; tap < KK; tap++) {
        __syncthreads();

        {
            float4* w4 = (float4*)wtile;
            const float4* src = wtg + tap * 1024;
            for (int l = tid; l < 1024; l += 128) w4[l] = src[l];
        }
        if (tid < 64) {
            int p = p0 + tid;
            int h = p / W, w = p % W;
            float oy = ob[(2 * tap) * HW + p];
            float ox = ob[(2 * tap + 1) * HW + p];
            float m  = ob[(2 * KK + tap) * HW + p];
            float py = (float)(h - PAD + tap / K) + oy;
            float px = (float)(w - PAD + tap % K) + ox;
            float y0f = floorf(py), x0f = floorf(px);
            float fy = py - y0f, fx = px - x0f;
            int y0 = (int)y0f, x0 = (int)x0f;
            int y1 = y0 + 1, x1 = x0 + 1;
            bool vy0 = (y0 >= 0) && (y0 < H);
            bool vy1 = (y1 >= 0) && (y1 < H);
            bool vx0 = (x0 >= 0) && (x0 < W);
            bool vx1 = (x1 >= 0) && (x1 < W);
            int y0c = min(max(y0, 0), H - 1), y1c = min(max(y1, 0), H - 1);
            int x0c = min(max(x0, 0), W - 1), x1c = min(max(x1, 0), W - 1);
            cw[tid][0] = (vy0 && vx0) ? (1.f - fy) * (1.f - fx) * m : 0.f;
            cw[tid][1] = (vy0 && vx1) ? (1.f - fy) * fx * m : 0.f;
            cw[tid][2] = (vy1 && vx0) ? fy * (1.f - fx) * m : 0.f;
            cw[tid][3] = (vy1 && vx1) ? fy * fx * m : 0.f;
            cidx[tid][0] = y0c * W + x0c;
            cidx[tid][1] = y0c * W + x1c;
            cidx[tid][2] = y1c * W + x0c;
            cidx[tid][3] = y1c * W + x1c;
        }
        __syncthreads();

        {
            int pix = tid & 63;
            int ch0 = (tid >> 6) * 32;
            float w0 = cw[pix][0], w1 = cw[pix][1];
            float w2 = cw[pix][2], w3 = cw[pix][3];
            int i0 = cidx[pix][0], i1 = cidx[pix][1];
            int i2 = cidx[pix][2], i3 = cidx[pix][3];
            #pragma unroll 4
            for (int cc = 0; cc < 32; cc++) {
                const float* xc = xb + (ch0 + cc) * HW;
                samp[(ch0 + cc) * 64 + pix] =
                    w0 * xc[i0] + w1 * xc[i1] + w2 * xc[i2] + w3 * xc[i3];
            }
        }
        __syncthreads();

        {
            const float4* s4 = (const float4*)samp;
            const float4* w4 = (const float4*)wtile;
            #pragma unroll 4
            for (int c = 0; c < 64; c++) {
                float4 s  = s4[c * 16 + pixg];
                float4 wa = w4[c * 16 + ocg * 2];
                float4 wb = w4[c * 16 + ocg * 2 + 1];
                float ww[8];
                ww[0] = wa.x; ww[1] = wa.y; ww[2] = wa.z; ww[3] = wa.w;
                ww[4] = wb.x; ww[5] = wb.y; ww[6] = wb.z; ww[7] = wb.w;
                #pragma unroll
                for (int j = 0; j < 8; j++) {
                    acc[j].x += ww[j] * s.x;
                    acc[j].y += ww[j] * s.y;
                    acc[j].z += ww[j] * s.z;
                    acc[j].w += ww[j] * s.w;
                }
            }
        }
    }

    float4* o4 = (float4*)out;
    #pragma unroll
    for (int j = 0; j < 8; j++) {
        int oc = ocg * 8 + j;
        o4[((b * 192 + obase + oc) * HW + p0) / 4 + pixg] = acc[j];
    }
}

__global__ __launch_bounds__(128) void deform_all(
    const float* __restrict__ x, float* __restrict__ out)
{
    __shared__ float samp[64 * 64];
    __shared__ float wtile[64 * 64];
    __shared__ float cw[64][4];
    __shared__ int   cidx[64][4];

    int bx = blockIdx.x;
    int b  = blockIdx.y;
    if (bx < 100)
        deform_body<7>(samp, wtile, cw, cidx, x, OFF7, WT7, out, 128, b, bx * 64);
    else if (bx < 200)
        deform_body<5>(samp, wtile, cw, cidx, x, OFF5, WT5, out, 64, b, (bx - 100) * 64);
    else
        deform_body<3>(samp, wtile, cw, cidx, x, OFF3, WT3, out, 0, b, (bx - 200) * 64);
}

// ============================================================
extern "C" void kernel_launch(void* const* d_in, const int* in_sizes, int n_in,
                              void* d_out, int out_size) {
    (void)in_sizes; (void)n_in; (void)out_size;
    const float* x       = (const float*)d_in[0];
    const float* w_off3  = (const float*)d_in[1];
    const float* b_off3  = (const float*)d_in[2];
    const float* w_msk3  = (const float*)d_in[3];
    const float* b_msk3  = (const float*)d_in[4];
    const float* w_dcn3  = (const float*)d_in[5];
    const float* w_off5  = (const float*)d_in[6];
    const float* b_off5  = (const float*)d_in[7];
    const float* w_msk5  = (const float*)d_in[8];
    const float* b_msk5  = (const float*)d_in[9];
    const float* w_dcn5  = (const float*)d_in[10];
    const float* w_off7  = (const float*)d_in[11];
    const float* b_off7  = (const float*)d_in[12];
    const float* w_msk7  = (const float*)d_in[13];
    const float* b_msk7  = (const float*)d_in[14];
    const float* w_dcn7  = (const float*)d_in[15];
    float* out = (float*)d_out;

    // 5 launches; observed capture rule (4th launch) lands on conv_all.
    conv_prep<<<(842240 + 255) / 256, 256>>>(w_off3, w_msk3, w_off5, w_msk5, w_off7, w_msk7);
    transpose_a<<<(34 * 4096 + 255) / 256, 256>>>(w_dcn3, w_dcn5);
    transpose_b<<<(49 * 4096 + 255) / 256, 256>>>(w_dcn7);

    conv_all<<<450, 256>>>(x, b_off3, b_msk3, b_off5, b_msk5, b_off7, b_msk7);

    deform_all<<<dim3(300, BATCH), 128>>>(x, out);
}

// round 13
// speedup vs baseline: 1.1631x; 1.0503x over previous
#include <cuda_runtime.h>
#include <math.h>

#define BATCH 2
#define C 64
#define H 80
#define W 80
#define HW 6400

// ---- scratch layout (floats) ----
#define OFF3 0
#define OFF5 345600            // 2*27*6400
#define OFF7 1305600           // + 2*75*6400
#define WT3  3187200           // + 2*147*6400
#define WT5  3224064           // + 9*4096
#define WT7  3326464           // + 25*4096
#define CW3  3527168           // + 49*4096   conv weights [ocb][c][tap][40]
#define CW5  3550208           // + 1*64*9*40
#define CW7  3742208           // + 3*64*25*40
#define SCRATCH_TOTAL 4369408  // + 5*64*49*40

__device__ __align__(16) float g_scratch[SCRATCH_TOTAL];

// ============================================================
// conv weight prep: w_off/w_msk -> [ocb][c][tap][40] (smem-ready, zero-padded)
// ============================================================
__global__ void conv_prep(const float* __restrict__ wo3, const float* __restrict__ wm3,
                          const float* __restrict__ wo5, const float* __restrict__ wm5,
                          const float* __restrict__ wo7, const float* __restrict__ wm7) {
    int i = blockIdx.x * 256 + threadIdx.x;
    const float *wo, *wm; int KK, base;
    if (i < 23040)       { wo = wo3; wm = wm3; KK = 9;  base = CW3; }
    else if (i < 215040) { wo = wo5; wm = wm5; KK = 25; base = CW5; i -= 23040; }
    else if (i < 842240) { wo = wo7; wm = wm7; KK = 49; base = CW7; i -= 215040; }
    else return;
    int ocl = i % 40;
    int t   = i / 40;
    int tap = t % KK;
    int t2  = t / KK;
    int c   = t2 & 63;
    int ocb = t2 >> 6;
    int oc  = ocb * 32 + ocl;
    float v = 0.f;
    if (ocl < 32) {
        if (oc < 2 * KK)      v = wo[(oc * 64 + c) * KK + tap];
        else if (oc < 3 * KK) v = wm[((oc - 2 * KK) * 64 + c) * KK + tap];
    }
    g_scratch[base + i] = v;
}

// ============================================================
// Merged transpose: w_dcn[oc][c][tap] -> wt[tap][c][oc]
// ============================================================
__global__ void transpose_all(const float* __restrict__ w3,
                              const float* __restrict__ w5,
                              const float* __restrict__ w7) {
    int i = blockIdx.x * 256 + threadIdx.x;
    if (i >= 83 * 4096) return;
    const float* src; int KK, base;
    if (i < 9 * 4096)       { src = w3; KK = 9;  base = WT3; }
    else if (i < 34 * 4096) { src = w5; KK = 25; base = WT5; i -= 9 * 4096; }
    else                    { src = w7; KK = 49; base = WT7; i -= 34 * 4096; }
    int tap = i >> 12;
    int r = i & 4095;
    int c = r >> 6;
    int oc = r & 63;
    g_scratch[base + i] = src[(oc * 64 + c) * KK + tap];
}

// ============================================================
// Conv body (unchanged from measured-best R12 version).
// ============================================================
#define CONV_SMEM_FLOATS 9864   // K=7: xp 4*22*23=2024 + ws 4*49*40=7840

template <int K>
__device__ __forceinline__ void conv_body(
    float* sm, const float* __restrict__ x,
    int cwbase, const float* __restrict__ b_off, const float* __restrict__ b_msk,
    int offbase, int id, int nOCB)
{
    constexpr int KK  = K * K;
    constexpr int CH  = 3 * KK;
    constexpr int PAD = K / 2;
    constexpr int PH  = 16 + K - 1;
    constexpr int PWP = PH + 1;
    constexpr int CC  = 4;
    constexpr int XPN = CC * PH * PWP;

    float* xp = sm;            // [CC][PH][PWP]
    float* ws = sm + XPN;      // [CC][KK][40]

    const int tid = threadIdx.x;
    const int bxx = id % 5;
    const int byy = (id / 5) % 5;
    const int z   = id / 25;
    const int b   = z / nOCB;
    const int ocb = z % nOCB;
    const int ty  = byy * 16;
    const int tx  = bxx * 16;

    const int ocg  = tid >> 6;
    const int pixg = tid & 63;
    const int py   = pixg & 15;
    const int px4  = (pixg >> 4) * 4;

    float acc[8][4];
    #pragma unroll
    for (int j = 0; j < 8; j++)
        #pragma unroll
        for (int i = 0; i < 4; i++) acc[j][i] = 0.f;

    for (int c0 = 0; c0 < C; c0 += CC) {
        __syncthreads();
        // x patch (zero-padded)
        for (int l = tid; l < CC * PH * PH; l += 256) {
            int cc = l / (PH * PH);
            int r  = l % (PH * PH);
            int ly = r / PH, lx = r % PH;
            int gy = ty - PAD + ly, gx = tx - PAD + lx;
            float v = 0.f;
            if (gy >= 0 && gy < H && gx >= 0 && gx < W)
                v = x[((b * C + c0 + cc) * H + gy) * W + gx];
            xp[(cc * PH + ly) * PWP + lx] = v;
        }
        // weights: contiguous float4 copy of this chunk's pre-transposed slice
        {
            constexpr int N4 = CC * KK * 10;   // (CC*KK*40)/4
            const float4* wsrc =
                (const float4*)&g_scratch[cwbase + ((ocb * 64 + c0) * KK) * 40];
            float4* wd = (float4*)ws;
            for (int l = tid; l < N4; l += 256) wd[l] = wsrc[l];
        }
        __syncthreads();

        #pragma unroll 1
        for (int cc = 0; cc < CC; cc++) {
            #pragma unroll 1
            for (int ky = 0; ky < K; ky++) {
                float xr[K + 3];
                const float* xrow = &xp[(cc * PH + py + ky) * PWP + px4];
                #pragma unroll
                for (int i = 0; i < K + 3; i++) xr[i] = xrow[i];
                #pragma unroll
                for (int kx = 0; kx < K; kx++) {
                    const float4* wv =
                        (const float4*)&ws[(cc * KK + ky * K + kx) * 40 + ocg * 8];
                    float4 wa = wv[0];
                    float4 wb = wv[1];
                    float ww[8];
                    ww[0] = wa.x; ww[1] = wa.y; ww[2] = wa.z; ww[3] = wa.w;
                    ww[4] = wb.x; ww[5] = wb.y; ww[6] = wb.z; ww[7] = wb.w;
                    #pragma unroll
                    for (int j = 0; j < 8; j++) {
                        acc[j][0] += ww[j] * xr[kx + 0];
                        acc[j][1] += ww[j] * xr[kx + 1];
                        acc[j][2] += ww[j] * xr[kx + 2];
                        acc[j][3] += ww[j] * xr[kx + 3];
                    }
                }
            }
        }
    }

    #pragma unroll 1
    for (int j = 0; j < 8; j++) {
        int oc = ocb * 32 + ocg * 8 + j;
        if (oc >= CH) break;
        bool ismask = (oc >= 2 * KK);
        float bias = ismask ? b_msk[oc - 2 * KK] : b_off[oc];
        float* dst = &g_scratch[offbase + (b * CH + oc) * HW + (ty + py) * W + tx + px4];
        #pragma unroll
        for (int i = 0; i < 4; i++) {
            float v = acc[j][i] + bias;
            if (ismask) v = 1.f / (1.f + __expf(-v));
            dst[i] = v;
        }
    }
}

__global__ __launch_bounds__(256, 4) void conv_all(
    const float* __restrict__ x,
    const float* __restrict__ bo3, const float* __restrict__ bm3,
    const float* __restrict__ bo5, const float* __restrict__ bm5,
    const float* __restrict__ bo7, const float* __restrict__ bm7)
{
    __shared__ float sm[CONV_SMEM_FLOATS];
    int bx = blockIdx.x;
    if (bx < 250)      conv_body<7>(sm, x, CW7, bo7, bm7, OFF7, bx, 5);
    else if (bx < 400) conv_body<5>(sm, x, CW5, bo5, bm5, OFF5, bx - 250, 3);
    else               conv_body<3>(sm, x, CW3, bo3, bm3, OFF3, bx - 400, 1);
}

// ============================================================
// Deform: 32 px, 64 oc per block, 128 threads (px-split for occupancy).
// smem 25.1KB -> ~8-9 blocks/SM resident vs 4 before.
// Each thread: 4 oc x 4 px accumulators.
// ============================================================
template <int K>
__device__ __forceinline__ void deform_body(
    float* samp,            // [64][32]
    float* wtile,           // [64][64]
    float (*cw)[4],         // [32][4]
    int (*cidx)[4],         // [32][4]
    const float* __restrict__ x, int offbase, int wtbase,
    float* __restrict__ out, int obase, int b, int p0)
{
    constexpr int KK  = K * K;
    constexpr int CH  = 3 * KK;
    constexpr int PAD = K / 2;

    const int tid   = threadIdx.x;
    const int pixg8 = tid & 7;    // float4 col 0..7 (px = pixg8*4)
    const int ocg16 = tid >> 3;   // 0..15 (4 oc each)

    float4 acc[4];
    #pragma unroll
    for (int j = 0; j < 4; j++) acc[j] = make_float4(0.f, 0.f, 0.f, 0.f);

    const float* xb = x + b * C * HW;
    const float4* wtg = (const float4*)(g_scratch + wtbase);
    const float* ob = g_scratch + offbase + b * CH * HW;

    #pragma unroll 1
    for (int tap = 0; tap < KK; tap++) {
        __syncthreads();

        // weight slice [c][oc] for this tap (16KB): 8 float4 per thread
        {
            float4* w4 = (float4*)wtile;
            const float4* src = wtg + tap * 1024;
            #pragma unroll
            for (int l = 0; l < 8; l++) w4[tid + l * 128] = src[tid + l * 128];
        }
        // per-pixel corner data (32 pixels)
        if (tid < 32) {
            int p = p0 + tid;
            int h = p / W, w = p % W;
            float oy = ob[(2 * tap) * HW + p];
            float ox = ob[(2 * tap + 1) * HW + p];
            float m  = ob[(2 * KK + tap) * HW + p];
            float py = (float)(h - PAD + tap / K) + oy;
            float px = (float)(w - PAD + tap % K) + ox;
            float y0f = floorf(py), x0f = floorf(px);
            float fy = py - y0f, fx = px - x0f;
            int y0 = (int)y0f, x0 = (int)x0f;
            int y1 = y0 + 1, x1 = x0 + 1;
            bool vy0 = (y0 >= 0) && (y0 < H);
            bool vy1 = (y1 >= 0) && (y1 < H);
            bool vx0 = (x0 >= 0) && (x0 < W);
            bool vx1 = (x1 >= 0) && (x1 < W);
            int y0c = min(max(y0, 0), H - 1), y1c = min(max(y1, 0), H - 1);
            int x0c = min(max(x0, 0), W - 1), x1c = min(max(x1, 0), W - 1);
            cw[tid][0] = (vy0 && vx0) ? (1.f - fy) * (1.f - fx) * m : 0.f;
            cw[tid][1] = (vy0 && vx1) ? (1.f - fy) * fx * m : 0.f;
            cw[tid][2] = (vy1 && vx0) ? fy * (1.f - fx) * m : 0.f;
            cw[tid][3] = (vy1 && vx1) ? fy * fx * m : 0.f;
            cidx[tid][0] = y0c * W + x0c;
            cidx[tid][1] = y0c * W + x1c;
            cidx[tid][2] = y1c * W + x0c;
            cidx[tid][3] = y1c * W + x1c;
        }
        __syncthreads();

        // bilinear gather: 1 pixel per thread, 16 channels each
        {
            int pix = tid & 31;
            int ch0 = (tid >> 5) * 16;
            float w0 = cw[pix][0], w1 = cw[pix][1];
            float w2 = cw[pix][2], w3 = cw[pix][3];
            int i0 = cidx[pix][0], i1 = cidx[pix][1];
            int i2 = cidx[pix][2], i3 = cidx[pix][3];
            #pragma unroll 4
            for (int cc = 0; cc < 16; cc++) {
                const float* xc = xb + (ch0 + cc) * HW;
                samp[(ch0 + cc) * 32 + pix] =
                    w0 * xc[i0] + w1 * xc[i1] + w2 * xc[i2] + w3 * xc[i3];
            }
        }
        __syncthreads();

        // GEMM accumulate: out[oc][pix] += wtile[c][oc] * samp[c][pix]
        {
            const float4* s4 = (const float4*)samp;
            const float4* w4 = (const float4*)wtile;
            #pragma unroll 4
            for (int c = 0; c < 64; c++) {
                float4 s = s4[c * 8 + pixg8];
                float4 w = w4[c * 16 + ocg16];
                acc[0].x += w.x * s.x; acc[0].y += w.x * s.y;
                acc[0].z += w.x * s.z; acc[0].w += w.x * s.w;
                acc[1].x += w.y * s.x; acc[1].y += w.y * s.y;
                acc[1].z += w.y * s.z; acc[1].w += w.y * s.w;
                acc[2].x += w.z * s.x; acc[2].y += w.z * s.y;
                acc[2].z += w.z * s.z; acc[2].w += w.z * s.w;
                acc[3].x += w.w * s.x; acc[3].y += w.w * s.y;
                acc[3].z += w.w * s.z; acc[3].w += w.w * s.w;
            }
        }
    }

    float4* o4 = (float4*)out;
    #pragma unroll
    for (int j = 0; j < 4; j++) {
        int oc = ocg16 * 4 + j;
        o4[((b * 192 + obase + oc) * HW + p0) / 4 + pixg8] = acc[j];
    }
}

__global__ __launch_bounds__(128, 8) void deform_all(
    const float* __restrict__ x, float* __restrict__ out)
{
    __shared__ float samp[64 * 32];
    __shared__ float wtile[64 * 64];
    __shared__ float cw[32][4];
    __shared__ int   cidx[32][4];

    int bx = blockIdx.x;
    int b  = blockIdx.y;
    if (bx < 200)
        deform_body<7>(samp, wtile, cw, cidx, x, OFF7, WT7, out, 128, b, bx * 32);
    else if (bx < 400)
        deform_body<5>(samp, wtile, cw, cidx, x, OFF5, WT5, out, 64, b, (bx - 200) * 32);
    else
        deform_body<3>(samp, wtile, cw, cidx, x, OFF3, WT3, out, 0, b, (bx - 400) * 32);
}

// ============================================================
extern "C" void kernel_launch(void* const* d_in, const int* in_sizes, int n_in,
                              void* d_out, int out_size) {
    (void)in_sizes; (void)n_in; (void)out_size;
    const float* x       = (const float*)d_in[0];
    const float* w_off3  = (const float*)d_in[1];
    const float* b_off3  = (const float*)d_in[2];
    const float* w_msk3  = (const float*)d_in[3];
    const float* b_msk3  = (const float*)d_in[4];
    const float* w_dcn3  = (const float*)d_in[5];
    const float* w_off5  = (const float*)d_in[6];
    const float* b_off5  = (const float*)d_in[7];
    const float* w_msk5  = (const float*)d_in[8];
    const float* b_msk5  = (const float*)d_in[9];
    const float* w_dcn5  = (const float*)d_in[10];
    const float* w_off7  = (const float*)d_in[11];
    const float* b_off7  = (const float*)d_in[12];
    const float* w_msk7  = (const float*)d_in[13];
    const float* b_msk7  = (const float*)d_in[14];
    const float* w_dcn7  = (const float*)d_in[15];
    float* out = (float*)d_out;

    // 4 launches; captured profile index (4th launch) = deform_all.
    conv_prep<<<(842240 + 255) / 256, 256>>>(w_off3, w_msk3, w_off5, w_msk5, w_off7, w_msk7);
    transpose_all<<<(83 * 4096 + 255) / 256, 256>>>(w_dcn3, w_dcn5, w_dcn7);

    conv_all<<<450, 256>>>(x, b_off3, b_msk3, b_off5, b_msk5, b_off7, b_msk7);

    deform_all<<<dim3(600, BATCH), 128>>>(x, out);
}